// round 6
// baseline (speedup 1.0000x reference)
#include <cuda_runtime.h>
#include <cuda_fp16.h>
#include <cstdint>

#define N_GENES 16384
#define N_REG   8192
#define D_MODEL 256
#define OUT_DIM 128
#define ALPHA   0.2f

#define TI 64                  // regulon rows per CTA
#define TJ 64                  // j per tile (MMA K)
#define JSPLIT 2
#define NJ (N_GENES / JSPLIT)  // 8192 j per CTA
#define NT (NJ / TJ)           // 128 tiles
#define STAGES 4

// smem layout (per CTA ~80.5 KB -> 2 CTAs/SM)
#define SM_P    0                      // 2 x 8 KB P double buffer
#define SM_V    16384                  // 4 x 16 KB V stages (fp16, swizzled 2x64-col atoms)
#define SM_S    81920                  // 64 floats
#define SMEM_BYTES 82304

// ---------------- device scratch ----------------
__device__ float  g_wh [N_GENES * OUT_DIM];
__device__ __align__(16) __half g_whh[N_GENES * OUT_DIM];   // w_h fp16, row-major
__device__ float  g_WT [OUT_DIM * D_MODEL];
__device__ float  g_wh1[N_REG];
__device__ float  g_wh2[N_GENES];
__device__ float  g_F1 [N_GENES];
__device__ float  g_F2 [N_GENES];
__device__ float  g_G1 [N_REG];
__device__ float  g_G2 [N_REG];
__device__ float  g_w2max;
__device__ float  g_Dp [JSPLIT][(size_t)N_REG * OUT_DIM];   // partial D
__device__ float  g_Sp [JSPLIT][N_REG];                     // partial S

// ---------------- helpers ----------------
static __device__ __forceinline__ uint32_t swz(uint32_t x) { return x ^ ((x >> 3) & 0x70); }
static __device__ __forceinline__ uint32_t smem_u32(const void* p) {
    return (uint32_t)__cvta_generic_to_shared(p);
}
static __device__ __forceinline__ uint64_t pk2(float x, float y) {
    uint64_t r; asm("mov.b64 %0, {%1, %2};" : "=l"(r) : "f"(x), "f"(y)); return r;
}
static __device__ __forceinline__ void fma2(uint64_t& acc, uint64_t a, uint64_t b) {
    asm volatile("fma.rn.f32x2 %0, %1, %2, %0;" : "+l"(acc) : "l"(a), "l"(b));
}

// ---------------- K0: W transpose ----------------
__global__ void k_transW(const float* __restrict__ W) {
    g_WT[threadIdx.x * D_MODEL + blockIdx.x] = W[blockIdx.x * OUT_DIM + threadIdx.x];
}

// ---------------- K1: w_h = input @ weights ----------------
__global__ void k_gemm1(const float* __restrict__ inp) {
    __shared__ __align__(16) float s_in[8][D_MODEL];
    const int c  = threadIdx.x;
    const int r0 = blockIdx.x * 8;
    for (int idx = c; idx < 8 * D_MODEL; idx += 128)
        s_in[idx >> 8][idx & 255] = inp[(size_t)(r0 + (idx >> 8)) * D_MODEL + (idx & 255)];
    __syncthreads();

    uint64_t acc[8];
    #pragma unroll
    for (int r = 0; r < 8; r++) acc[r] = 0ull;

    const float4* wt4 = (const float4*)&g_WT[c * D_MODEL];
    #pragma unroll 2
    for (int k4 = 0; k4 < D_MODEL / 4; k4++) {
        float4 wv = __ldg(&wt4[k4]);
        uint64_t w01 = pk2(wv.x, wv.y);
        uint64_t w23 = pk2(wv.z, wv.w);
        #pragma unroll
        for (int r = 0; r < 8; r++) {
            ulonglong2 a2 = *(const ulonglong2*)&s_in[r][k4 * 4];
            fma2(acc[r], a2.x, w01);
            fma2(acc[r], a2.y, w23);
        }
    }
    #pragma unroll
    for (int r = 0; r < 8; r++) {
        float lo = __uint_as_float((uint32_t)acc[r]);
        float hi = __uint_as_float((uint32_t)(acc[r] >> 32));
        float v = lo + hi;
        g_wh [(size_t)(r0 + r) * OUT_DIM + c] = v;
        g_whh[(size_t)(r0 + r) * OUT_DIM + c] = __float2half(v);
    }
}

// ---------------- K2: wh1, wh2 ----------------
__global__ void k_wh12(const float* __restrict__ a) {
    const int row  = blockIdx.x * 8 + (threadIdx.x >> 5);
    const int lane = threadIdx.x & 31;
    const float* r = g_wh + (size_t)row * OUT_DIM;
    float s1 = 0.f, s2 = 0.f;
    #pragma unroll
    for (int c = lane; c < OUT_DIM; c += 32) {
        float v = r[c];
        s1 = fmaf(v, a[c], s1);
        s2 = fmaf(v, a[OUT_DIM + c], s2);
    }
    #pragma unroll
    for (int o = 16; o; o >>= 1) {
        s1 += __shfl_xor_sync(0xffffffffu, s1, o);
        s2 += __shfl_xor_sync(0xffffffffu, s2, o);
    }
    if (lane == 0) {
        if (row < N_REG) g_wh1[row] = s1;
        g_wh2[row] = s2;
    }
}

// ---------------- K3: max over wh2 ----------------
__global__ void k_max() {
    __shared__ float sm[32];
    float m = -1e30f;
    for (int j = threadIdx.x; j < N_GENES; j += blockDim.x) m = fmaxf(m, g_wh2[j]);
    #pragma unroll
    for (int o = 16; o; o >>= 1) m = fmaxf(m, __shfl_xor_sync(0xffffffffu, m, o));
    if ((threadIdx.x & 31) == 0) sm[threadIdx.x >> 5] = m;
    __syncthreads();
    if (threadIdx.x < 32) {
        float v = (threadIdx.x < (blockDim.x >> 5)) ? sm[threadIdx.x] : -1e30f;
        #pragma unroll
        for (int o = 16; o; o >>= 1) v = fmaxf(v, __shfl_xor_sync(0xffffffffu, v, o));
        if (threadIdx.x == 0) g_w2max = v;
    }
}

// ---------------- K4: exp factor tables ----------------
__global__ void k_factors() {
    const int j = blockIdx.x * 256 + threadIdx.x;
    const float w2m = g_w2max;
    if (j < N_GENES) {
        float w2 = g_wh2[j];
        g_F1[j] = expf(w2);
        g_F2[j] = expf(ALPHA * w2);
    }
    if (j < N_REG) {
        float w1 = g_wh1[j];
        float x  = w1 + w2m;
        float B  = x > 0.f ? x : ALPHA * x;
        g_G1[j] = expf(w1 - B);
        g_G2[j] = expf(ALPHA * w1 - B);
    }
}

// ---------------- K5: fused masked-softmax attention ----------------
__global__ void __launch_bounds__(256, 2)
k_attn(const float* __restrict__ adj) {
    extern __shared__ char smem[];
    const uint32_t sb = smem_u32(smem);
    float* sS = (float*)(smem + SM_S);

    const int t    = threadIdx.x;
    const int lane = t & 31, warp = t >> 5;   // 8 warps
    const int i0   = (blockIdx.x >> 1) * TI;
    const int jh   = blockIdx.x & 1;
    const int j0b  = jh * NJ;
    const int rh   = lane >> 4;               // row half within warp's 8 rows
    const int q    = lane & 15;               // col quad (4 cols)

    // V stage loader (16 KB per tile); ALWAYS commits a group
    auto load_stage = [&](int jt) {
        if (jt < NT) {
            const int st = jt & (STAGES - 1);
            const int jo = j0b + jt * TJ;
            const uint32_t VB = sb + SM_V + st * 16384;
            #pragma unroll
            for (int u = 0; u < 4; u++) {
                const int idx = t + u * 256;
                const int row = idx >> 4, seg = idx & 15;
                const __half* vsrc = &g_whh[(size_t)(jo + row) * OUT_DIM + seg * 8];
                const uint32_t vdst = VB + (seg >> 3) * 8192 + swz(row * 128 + (seg & 7) * 16);
                asm volatile("cp.async.cg.shared.global [%0], [%1], 16;" :: "r"(vdst), "l"(vsrc));
            }
        }
        asm volatile("cp.async.commit_group;" ::: "memory");
    };

    // P-build rows: warp*8 + rh*4 + r  (r = 0..3)
    float Tr[4], G1r[4], G2r[4], sacc[4];
    #pragma unroll
    for (int r = 0; r < 4; r++) {
        const int i = i0 + warp * 8 + rh * 4 + r;
        Tr[r]  = g_wh1[i];
        G1r[r] = g_G1[i];
        G2r[r] = g_G2[i];
        sacc[r] = 0.f;
    }

    const float* adjp = adj + (size_t)(i0 + warp * 8 + rh * 4) * N_GENES + j0b + q * 4;

    // MMA tiling: warp -> rows wi*32 (2 m16 frags), cols wc*32
    const int wi = warp >> 2, wc = warp & 3;
    float d[2][4][4];
    #pragma unroll
    for (int ah = 0; ah < 2; ah++)
        #pragma unroll
        for (int n = 0; n < 4; n++)
            #pragma unroll
            for (int k = 0; k < 4; k++) d[ah][n][k] = 0.f;

    // prefetch adj + factor tables for tile 0
    float4 av[4], w2q, f1q, f2q;
    #pragma unroll
    for (int r = 0; r < 4; r++)
        av[r] = __ldg((const float4*)(adjp + (size_t)r * N_GENES));
    w2q = *(const float4*)&g_wh2[j0b + q * 4];
    f1q = *(const float4*)&g_F1 [j0b + q * 4];
    f2q = *(const float4*)&g_F2 [j0b + q * 4];

    // prologue: fill 3 V stages
    load_stage(0);
    load_stage(1);
    load_stage(2);

    for (int jt = 0; jt < NT; jt++) {
        const uint32_t PB = sb + SM_P + (jt & 1) * 8192;
        const uint32_t VB = sb + SM_V + (jt & (STAGES - 1)) * 16384;

        asm volatile("cp.async.wait_group 2;" ::: "memory");
        __syncthreads();

        load_stage(jt + 3);

        // ---- build P tile (4 rows x 4 cols per thread) ----
        #pragma unroll
        for (int r = 0; r < 4; r++) {
            const float T = Tr[r], G1 = G1r[r], G2 = G2r[r];
            float x0 = T + w2q.x, x1 = T + w2q.y, x2 = T + w2q.z, x3 = T + w2q.w;
            float e0 = fmaxf(G1 * f1q.x, G2 * f2q.x);   // exp(lrelu(x)-B), monotone split
            float e1 = fmaxf(G1 * f1q.y, G2 * f2q.y);
            float e2 = fmaxf(G1 * f1q.z, G2 * f2q.z);
            float e3 = fmaxf(G1 * f1q.w, G2 * f2q.w);
            float p0 = (av[r].x != 0.f && x0 != 0.f) ? e0 : 0.f;
            float p1 = (av[r].y != 0.f && x1 != 0.f) ? e1 : 0.f;
            float p2 = (av[r].z != 0.f && x2 != 0.f) ? e2 : 0.f;
            float p3 = (av[r].w != 0.f && x3 != 0.f) ? e3 : 0.f;
            sacc[r] += (p0 + p1) + (p2 + p3);
            __half2 h01 = __floats2half2_rn(p0, p1);
            __half2 h23 = __floats2half2_rn(p2, p3);
            asm volatile("st.shared.v2.b32 [%0], {%1, %2};"
                         :: "r"(PB + swz((warp * 8 + rh * 4 + r) * 128 + q * 8)),
                            "r"(*(uint32_t*)&h01), "r"(*(uint32_t*)&h23));
        }

        // ---- prefetch adj + factors for tile jt+1 (hidden under MMA + next wait) ----
        if (jt + 1 < NT) {
            const int jo = (jt + 1) * TJ;
            #pragma unroll
            for (int r = 0; r < 4; r++)
                av[r] = __ldg((const float4*)(adjp + (size_t)r * N_GENES + jo));
            w2q = *(const float4*)&g_wh2[j0b + jo + q * 4];
            f1q = *(const float4*)&g_F1 [j0b + jo + q * 4];
            f2q = *(const float4*)&g_F2 [j0b + jo + q * 4];
        }
        __syncthreads();   // P complete

        // ---- MMA: D(32x32 per warp) += P(32x64) @ V(64x32) ----
        #pragma unroll
        for (int ks = 0; ks < 4; ks++) {
            uint32_t afr[2][4];
            #pragma unroll
            for (int ah = 0; ah < 2; ah++) {
                const uint32_t aaddr = PB + swz((wi * 32 + ah * 16 + (lane & 15)) * 128
                                                + ks * 32 + (lane >> 4) * 16);
                asm volatile("ldmatrix.sync.aligned.m8n8.x4.shared.b16 {%0,%1,%2,%3},[%4];\n"
                             : "=r"(afr[ah][0]), "=r"(afr[ah][1]),
                               "=r"(afr[ah][2]), "=r"(afr[ah][3]) : "r"(aaddr));
            }
            uint32_t bfr[8];
            const int atom = wc >> 1;
            const int cin0 = (wc & 1) * 32 + (lane >> 4) * 8;
            const uint32_t brow = (ks * 16 + (lane & 15)) * 128;
            const uint32_t baddr0 = VB + atom * 8192 + swz(brow + cin0 * 2);
            asm volatile("ldmatrix.sync.aligned.m8n8.x4.trans.shared.b16 {%0,%1,%2,%3},[%4];\n"
                         : "=r"(bfr[0]), "=r"(bfr[1]), "=r"(bfr[2]), "=r"(bfr[3]) : "r"(baddr0));
            const uint32_t baddr1 = VB + atom * 8192 + swz(brow + (cin0 + 16) * 2);
            asm volatile("ldmatrix.sync.aligned.m8n8.x4.trans.shared.b16 {%0,%1,%2,%3},[%4];\n"
                         : "=r"(bfr[4]), "=r"(bfr[5]), "=r"(bfr[6]), "=r"(bfr[7]) : "r"(baddr1));
            #pragma unroll
            for (int ah = 0; ah < 2; ah++)
                #pragma unroll
                for (int n = 0; n < 4; n++) {
                    asm volatile(
                        "mma.sync.aligned.m16n8k16.row.col.f32.f16.f16.f32 "
                        "{%0,%1,%2,%3},{%4,%5,%6,%7},{%8,%9},{%0,%1,%2,%3};\n"
                        : "+f"(d[ah][n][0]), "+f"(d[ah][n][1]),
                          "+f"(d[ah][n][2]), "+f"(d[ah][n][3])
                        : "r"(afr[ah][0]), "r"(afr[ah][1]), "r"(afr[ah][2]), "r"(afr[ah][3]),
                          "r"(bfr[n * 2]), "r"(bfr[n * 2 + 1]));
                }
        }
    }

    // ---- S: reduce over 16 lanes (col quads) sharing each row ----
    #pragma unroll
    for (int r = 0; r < 4; r++) {
        float v = sacc[r];
        v += __shfl_xor_sync(0xffffffffu, v, 8);
        v += __shfl_xor_sync(0xffffffffu, v, 4);
        v += __shfl_xor_sync(0xffffffffu, v, 2);
        v += __shfl_xor_sync(0xffffffffu, v, 1);
        if (q == 0) g_Sp[jh][i0 + warp * 8 + rh * 4 + r] = v;
    }

    // ---- store partial D (unnormalized) ----
    float* dp = g_Dp[jh];
    #pragma unroll
    for (int ah = 0; ah < 2; ah++) {
        const int r1 = wi * 32 + ah * 16 + (lane >> 2);
        #pragma unroll
        for (int n = 0; n < 4; n++) {
            const int c = wc * 32 + n * 8 + (lane & 3) * 2;
            *(float2*)&dp[(size_t)(i0 + r1) * OUT_DIM + c]     = make_float2(d[ah][n][0], d[ah][n][1]);
            *(float2*)&dp[(size_t)(i0 + r1 + 8) * OUT_DIM + c] = make_float2(d[ah][n][2], d[ah][n][3]);
        }
    }
}

// ---------------- K6: combine j-halves, normalize, ELU ----------------
__global__ void k_combine(float* __restrict__ out) {
    const int i = blockIdx.x, c = threadIdx.x;
    const float s = g_Sp[0][i] + g_Sp[1][i];
    const size_t idx = (size_t)i * OUT_DIM + c;
    float v = (g_Dp[0][idx] + g_Dp[1][idx]) / s;
    out[idx] = v > 0.f ? v : expm1f(v);
}

// ---------------- launch ----------------
extern "C" void kernel_launch(void* const* d_in, const int* in_sizes, int n_in,
                              void* d_out, int out_size) {
    const float* inp = (const float*)d_in[0];   // [16384, 256]
    const float* adj = (const float*)d_in[1];   // [8192, 16384]
    const float* W   = (const float*)d_in[2];   // [256, 128]
    const float* a   = (const float*)d_in[3];   // [256, 1]
    float* out = (float*)d_out;                 // [8192, 128]

    cudaFuncSetAttribute(k_attn, cudaFuncAttributeMaxDynamicSharedMemorySize, SMEM_BYTES);

    k_transW <<<D_MODEL, OUT_DIM>>>(W);
    k_gemm1  <<<N_GENES / 8, 128>>>(inp);
    k_wh12   <<<N_GENES / 8, 256>>>(a);
    k_max    <<<1, 1024>>>();
    k_factors<<<N_GENES / 256, 256>>>();
    k_attn   <<<(N_REG / TI) * JSPLIT, 256, SMEM_BYTES>>>(adj);
    k_combine<<<N_REG, OUT_DIM>>>(out);
}

// round 7
// speedup vs baseline: 1.1268x; 1.1268x over previous
#include <cuda_runtime.h>
#include <cuda_fp16.h>
#include <cstdint>

#define N_GENES 16384
#define N_REG   8192
#define D_MODEL 256
#define OUT_DIM 128
#define ALPHA   0.2f

#define TI 64                  // regulon rows per CTA
#define TJ 64                  // j per tile (MMA K)
#define JSPLIT 2
#define NJ (N_GENES / JSPLIT)  // 8192 j per CTA
#define NT (NJ / TJ)           // 128 tiles
#define STAGES 4

// smem layout (per CTA ~80.5 KB -> 2 CTAs/SM)
#define SM_P    0                      // 2 x 8 KB P double buffer
#define SM_V    16384                  // 4 x 16 KB V stages (fp16, swizzled 2x64-col atoms)
#define SMEM_BYTES 82304

// ---------------- device scratch ----------------
__device__ float  g_wh [N_GENES * OUT_DIM];
__device__ __align__(16) __half g_whh[N_GENES * OUT_DIM];   // w_h fp16, row-major
__device__ float  g_wh1[N_REG];
__device__ float  g_wh2[N_GENES];
__device__ float  g_F1 [N_GENES];
__device__ float  g_F2 [N_GENES];
__device__ float  g_G1 [N_REG];
__device__ float  g_G2 [N_REG];
__device__ unsigned g_w2max_bits;
__device__ float  g_Dp [JSPLIT][(size_t)N_REG * OUT_DIM];   // partial D
__device__ float  g_Sp [JSPLIT][N_REG];                     // partial S

// ---------------- helpers ----------------
static __device__ __forceinline__ uint32_t swz(uint32_t x) { return x ^ ((x >> 3) & 0x70); }
static __device__ __forceinline__ uint32_t smem_u32(const void* p) {
    return (uint32_t)__cvta_generic_to_shared(p);
}
static __device__ __forceinline__ uint64_t pk2(float x, float y) {
    uint64_t r; asm("mov.b64 %0, {%1, %2};" : "=l"(r) : "f"(x), "f"(y)); return r;
}
static __device__ __forceinline__ void fma2(uint64_t& acc, uint64_t a, uint64_t b) {
    asm volatile("fma.rn.f32x2 %0, %1, %2, %0;" : "+l"(acc) : "l"(a), "l"(b));
}
// order-preserving float<->uint encode for atomicMax
static __device__ __forceinline__ unsigned fenc(float f) {
    unsigned u = __float_as_uint(f);
    return (u & 0x80000000u) ? ~u : (u | 0x80000000u);
}
static __device__ __forceinline__ float fdec(unsigned k) {
    unsigned u = (k & 0x80000000u) ? (k ^ 0x80000000u) : ~k;
    return __uint_as_float(u);
}

// ---------------- K1: w_h = input @ weights (W read direct, transposed smem) ----------------
__global__ void k_gemm1(const float* __restrict__ inp, const float* __restrict__ W) {
    __shared__ __align__(16) float s_t[D_MODEL][8];   // [k][r]
    const int c  = threadIdx.x;          // output column 0..127
    const int r0 = blockIdx.x * 8;
    if (blockIdx.x == 0 && c == 0) g_w2max_bits = 0u;   // reset for this call
    #pragma unroll
    for (int u = 0; u < 16; u++) {
        const int idx = c + u * 128;
        const int r = idx >> 8, k = idx & 255;
        s_t[k][r] = inp[(size_t)(r0 + r) * D_MODEL + k];
    }
    __syncthreads();

    uint64_t a01 = 0, a23 = 0, a45 = 0, a67 = 0;
    #pragma unroll 4
    for (int k = 0; k < D_MODEL; k++) {
        const float w = __ldg(&W[k * OUT_DIM + c]);
        const uint64_t ww = pk2(w, w);
        ulonglong2 lo = *(const ulonglong2*)&s_t[k][0];
        ulonglong2 hi = *(const ulonglong2*)&s_t[k][4];
        fma2(a01, lo.x, ww);
        fma2(a23, lo.y, ww);
        fma2(a45, hi.x, ww);
        fma2(a67, hi.y, ww);
    }
    float v[8];
    v[0] = __uint_as_float((uint32_t)a01); v[1] = __uint_as_float((uint32_t)(a01 >> 32));
    v[2] = __uint_as_float((uint32_t)a23); v[3] = __uint_as_float((uint32_t)(a23 >> 32));
    v[4] = __uint_as_float((uint32_t)a45); v[5] = __uint_as_float((uint32_t)(a45 >> 32));
    v[6] = __uint_as_float((uint32_t)a67); v[7] = __uint_as_float((uint32_t)(a67 >> 32));
    #pragma unroll
    for (int r = 0; r < 8; r++) {
        g_wh [(size_t)(r0 + r) * OUT_DIM + c] = v[r];
        g_whh[(size_t)(r0 + r) * OUT_DIM + c] = __float2half(v[r]);
    }
}

// ---------------- K2: wh1, wh2 + global max(wh2) via atomic ----------------
__global__ void k_wh12(const float* __restrict__ a) {
    __shared__ float sred[8];
    const int warp = threadIdx.x >> 5;
    const int row  = blockIdx.x * 8 + warp;
    const int lane = threadIdx.x & 31;
    const float* r = g_wh + (size_t)row * OUT_DIM;
    float s1 = 0.f, s2 = 0.f;
    #pragma unroll
    for (int c = lane; c < OUT_DIM; c += 32) {
        float v = r[c];
        s1 = fmaf(v, a[c], s1);
        s2 = fmaf(v, a[OUT_DIM + c], s2);
    }
    #pragma unroll
    for (int o = 16; o; o >>= 1) {
        s1 += __shfl_xor_sync(0xffffffffu, s1, o);
        s2 += __shfl_xor_sync(0xffffffffu, s2, o);
    }
    if (lane == 0) {
        if (row < N_REG) g_wh1[row] = s1;
        g_wh2[row] = s2;
        sred[warp] = s2;
    }
    __syncthreads();
    if (threadIdx.x == 0) {
        float m = sred[0];
        #pragma unroll
        for (int w = 1; w < 8; w++) m = fmaxf(m, sred[w]);
        atomicMax(&g_w2max_bits, fenc(m));
    }
}

// ---------------- K3: exp factor tables ----------------
__global__ void k_factors() {
    const int j = blockIdx.x * 256 + threadIdx.x;
    const float w2m = fdec(g_w2max_bits);
    if (j < N_GENES) {
        float w2 = g_wh2[j];
        g_F1[j] = expf(w2);
        g_F2[j] = expf(ALPHA * w2);
    }
    if (j < N_REG) {
        float w1 = g_wh1[j];
        float x  = w1 + w2m;
        float B  = x > 0.f ? x : ALPHA * x;
        g_G1[j] = expf(w1 - B);
        g_G2[j] = expf(ALPHA * w1 - B);
    }
}

// ---------------- K4: fused masked-softmax attention (fp16-acc HMMA + fp32 flush) ---------
__global__ void __launch_bounds__(256, 2)
k_attn(const float* __restrict__ adj) {
    extern __shared__ char smem[];
    const uint32_t sb = smem_u32(smem);

    const int t    = threadIdx.x;
    const int lane = t & 31, warp = t >> 5;   // 8 warps
    const int i0   = (blockIdx.x >> 1) * TI;
    const int jh   = blockIdx.x & 1;
    const int j0b  = jh * NJ;
    const int rh   = lane >> 4;               // row half within warp's 8 rows
    const int q    = lane & 15;               // col quad (4 cols)

    // V stage loader (16 KB per tile); ALWAYS commits a group
    auto load_stage = [&](int jt) {
        if (jt < NT) {
            const int st = jt & (STAGES - 1);
            const int jo = j0b + jt * TJ;
            const uint32_t VB = sb + SM_V + st * 16384;
            #pragma unroll
            for (int u = 0; u < 4; u++) {
                const int idx = t + u * 256;
                const int row = idx >> 4, seg = idx & 15;
                const __half* vsrc = &g_whh[(size_t)(jo + row) * OUT_DIM + seg * 8];
                const uint32_t vdst = VB + (seg >> 3) * 8192 + swz(row * 128 + (seg & 7) * 16);
                asm volatile("cp.async.cg.shared.global [%0], [%1], 16;" :: "r"(vdst), "l"(vsrc));
            }
        }
        asm volatile("cp.async.commit_group;" ::: "memory");
    };

    // P-build rows: warp*8 + rh*4 + r  (r = 0..3)
    float Tr[4], G1r[4], G2r[4], sacc[4];
    #pragma unroll
    for (int r = 0; r < 4; r++) {
        const int i = i0 + warp * 8 + rh * 4 + r;
        Tr[r]  = g_wh1[i];
        G1r[r] = g_G1[i];
        G2r[r] = g_G2[i];
        sacc[r] = 0.f;
    }

    const float* adjp = adj + (size_t)(i0 + warp * 8 + rh * 4) * N_GENES + j0b + q * 4;

    // MMA tiling: warp -> rows wi*32 (2 m16 frags), cols wc*32
    const int wi = warp >> 2, wc = warp & 3;
    float d[2][4][4];
    #pragma unroll
    for (int ah = 0; ah < 2; ah++)
        #pragma unroll
        for (int n = 0; n < 4; n++)
            #pragma unroll
            for (int k = 0; k < 4; k++) d[ah][n][k] = 0.f;

    // prefetch adj + factor tables for tile 0
    float4 av[4], w2q, f1q, f2q;
    #pragma unroll
    for (int r = 0; r < 4; r++)
        av[r] = __ldg((const float4*)(adjp + (size_t)r * N_GENES));
    w2q = *(const float4*)&g_wh2[j0b + q * 4];
    f1q = *(const float4*)&g_F1 [j0b + q * 4];
    f2q = *(const float4*)&g_F2 [j0b + q * 4];

    // prologue: fill 3 V stages
    load_stage(0);
    load_stage(1);
    load_stage(2);

    for (int jt = 0; jt < NT; jt++) {
        const uint32_t PB = sb + SM_P + (jt & 1) * 8192;
        const uint32_t VB = sb + SM_V + (jt & (STAGES - 1)) * 16384;

        asm volatile("cp.async.wait_group 2;" ::: "memory");
        __syncthreads();

        load_stage(jt + 3);

        // ---- build P tile (4 rows x 4 cols per thread) ----
        #pragma unroll
        for (int r = 0; r < 4; r++) {
            const float T = Tr[r], G1 = G1r[r], G2 = G2r[r];
            float x0 = T + w2q.x, x1 = T + w2q.y, x2 = T + w2q.z, x3 = T + w2q.w;
            float e0 = fmaxf(G1 * f1q.x, G2 * f2q.x);   // exp(lrelu(x)-B), monotone split
            float e1 = fmaxf(G1 * f1q.y, G2 * f2q.y);
            float e2 = fmaxf(G1 * f1q.z, G2 * f2q.z);
            float e3 = fmaxf(G1 * f1q.w, G2 * f2q.w);
            float p0 = (av[r].x != 0.f && x0 != 0.f) ? e0 : 0.f;
            float p1 = (av[r].y != 0.f && x1 != 0.f) ? e1 : 0.f;
            float p2 = (av[r].z != 0.f && x2 != 0.f) ? e2 : 0.f;
            float p3 = (av[r].w != 0.f && x3 != 0.f) ? e3 : 0.f;
            sacc[r] += (p0 + p1) + (p2 + p3);
            __half2 h01 = __floats2half2_rn(p0, p1);
            __half2 h23 = __floats2half2_rn(p2, p3);
            asm volatile("st.shared.v2.b32 [%0], {%1, %2};"
                         :: "r"(PB + swz((warp * 8 + rh * 4 + r) * 128 + q * 8)),
                            "r"(*(uint32_t*)&h01), "r"(*(uint32_t*)&h23));
        }

        // ---- prefetch adj + factors for tile jt+1 (hidden under MMA + next wait) ----
        if (jt + 1 < NT) {
            const int jo = (jt + 1) * TJ;
            #pragma unroll
            for (int r = 0; r < 4; r++)
                av[r] = __ldg((const float4*)(adjp + (size_t)r * N_GENES + jo));
            w2q = *(const float4*)&g_wh2[j0b + jo + q * 4];
            f1q = *(const float4*)&g_F1 [j0b + jo + q * 4];
            f2q = *(const float4*)&g_F2 [j0b + jo + q * 4];
        }
        __syncthreads();   // P complete

        // ---- MMA: fp16 accumulate within the tile, flush to fp32 after ----
        uint32_t dh[2][4][2];
        #pragma unroll
        for (int ah = 0; ah < 2; ah++)
            #pragma unroll
            for (int n = 0; n < 4; n++) { dh[ah][n][0] = 0u; dh[ah][n][1] = 0u; }

        #pragma unroll
        for (int ks = 0; ks < 4; ks++) {
            uint32_t afr[2][4];
            #pragma unroll
            for (int ah = 0; ah < 2; ah++) {
                const uint32_t aaddr = PB + swz((wi * 32 + ah * 16 + (lane & 15)) * 128
                                                + ks * 32 + (lane >> 4) * 16);
                asm volatile("ldmatrix.sync.aligned.m8n8.x4.shared.b16 {%0,%1,%2,%3},[%4];\n"
                             : "=r"(afr[ah][0]), "=r"(afr[ah][1]),
                               "=r"(afr[ah][2]), "=r"(afr[ah][3]) : "r"(aaddr));
            }
            uint32_t bfr[8];
            const int atom = wc >> 1;
            const int cin0 = (wc & 1) * 32 + (lane >> 4) * 8;
            const uint32_t brow = (ks * 16 + (lane & 15)) * 128;
            const uint32_t baddr0 = VB + atom * 8192 + swz(brow + cin0 * 2);
            asm volatile("ldmatrix.sync.aligned.m8n8.x4.trans.shared.b16 {%0,%1,%2,%3},[%4];\n"
                         : "=r"(bfr[0]), "=r"(bfr[1]), "=r"(bfr[2]), "=r"(bfr[3]) : "r"(baddr0));
            const uint32_t baddr1 = VB + atom * 8192 + swz(brow + (cin0 + 16) * 2);
            asm volatile("ldmatrix.sync.aligned.m8n8.x4.trans.shared.b16 {%0,%1,%2,%3},[%4];\n"
                         : "=r"(bfr[4]), "=r"(bfr[5]), "=r"(bfr[6]), "=r"(bfr[7]) : "r"(baddr1));
            #pragma unroll
            for (int ah = 0; ah < 2; ah++)
                #pragma unroll
                for (int n = 0; n < 4; n++) {
                    asm volatile(
                        "mma.sync.aligned.m16n8k16.row.col.f16.f16.f16.f16 "
                        "{%0,%1},{%2,%3,%4,%5},{%6,%7},{%0,%1};\n"
                        : "+r"(dh[ah][n][0]), "+r"(dh[ah][n][1])
                        : "r"(afr[ah][0]), "r"(afr[ah][1]), "r"(afr[ah][2]), "r"(afr[ah][3]),
                          "r"(bfr[n * 2]), "r"(bfr[n * 2 + 1]));
                }
        }

        // flush fp16 tile accumulators into fp32
        #pragma unroll
        for (int ah = 0; ah < 2; ah++)
            #pragma unroll
            for (int n = 0; n < 4; n++) {
                float2 lo = __half22float2(*(__half2*)&dh[ah][n][0]);
                float2 hi = __half22float2(*(__half2*)&dh[ah][n][1]);
                d[ah][n][0] += lo.x; d[ah][n][1] += lo.y;
                d[ah][n][2] += hi.x; d[ah][n][3] += hi.y;
            }
    }

    // ---- S: reduce over 16 lanes (col quads) sharing each row ----
    #pragma unroll
    for (int r = 0; r < 4; r++) {
        float v = sacc[r];
        v += __shfl_xor_sync(0xffffffffu, v, 8);
        v += __shfl_xor_sync(0xffffffffu, v, 4);
        v += __shfl_xor_sync(0xffffffffu, v, 2);
        v += __shfl_xor_sync(0xffffffffu, v, 1);
        if (q == 0) g_Sp[jh][i0 + warp * 8 + rh * 4 + r] = v;
    }

    // ---- store partial D (unnormalized) ----
    float* dp = g_Dp[jh];
    #pragma unroll
    for (int ah = 0; ah < 2; ah++) {
        const int r1 = wi * 32 + ah * 16 + (lane >> 2);
        #pragma unroll
        for (int n = 0; n < 4; n++) {
            const int c = wc * 32 + n * 8 + (lane & 3) * 2;
            *(float2*)&dp[(size_t)(i0 + r1) * OUT_DIM + c]     = make_float2(d[ah][n][0], d[ah][n][1]);
            *(float2*)&dp[(size_t)(i0 + r1 + 8) * OUT_DIM + c] = make_float2(d[ah][n][2], d[ah][n][3]);
        }
    }
}

// ---------------- K5: combine j-halves, normalize, ELU ----------------
__global__ void k_combine(float* __restrict__ out) {
    const int i = blockIdx.x, c = threadIdx.x;
    const float s = g_Sp[0][i] + g_Sp[1][i];
    const size_t idx = (size_t)i * OUT_DIM + c;
    float v = (g_Dp[0][idx] + g_Dp[1][idx]) / s;
    out[idx] = v > 0.f ? v : expm1f(v);
}

// ---------------- launch ----------------
extern "C" void kernel_launch(void* const* d_in, const int* in_sizes, int n_in,
                              void* d_out, int out_size) {
    const float* inp = (const float*)d_in[0];   // [16384, 256]
    const float* adj = (const float*)d_in[1];   // [8192, 16384]
    const float* W   = (const float*)d_in[2];   // [256, 128]
    const float* a   = (const float*)d_in[3];   // [256, 1]
    float* out = (float*)d_out;                 // [8192, 128]

    cudaFuncSetAttribute(k_attn, cudaFuncAttributeMaxDynamicSharedMemorySize, SMEM_BYTES);

    k_gemm1  <<<N_GENES / 8, 128>>>(inp, W);                 // launch 1
    k_wh12   <<<N_GENES / 8, 256>>>(a);                      // launch 2 (incl. max)
    k_factors<<<N_GENES / 256, 256>>>();                     // launch 3
    k_attn   <<<(N_REG / TI) * JSPLIT, 256, SMEM_BYTES>>>(adj);   // launch 4 (ncu target)
    k_combine<<<N_REG, OUT_DIM>>>(out);                      // launch 5
}